// round 14
// baseline (speedup 1.0000x reference)
#include <cuda_runtime.h>
#include <float.h>

#define POOLW 7
#define IMG_W 2048
#define IMG_HW (2048 * 2048)
#define NTHREADS 224          // 7 warps; warp w owns slices ic = w and ic = w+7
#define MAXW 96

__global__ __launch_bounds__(NTHREADS)
void roi_pool_fc_kernel(const float* __restrict__ feature,
                        const float* __restrict__ boxes,
                        const int*   __restrict__ coords,
                        const float* __restrict__ fc_w,
                        const float* __restrict__ fc_b,
                        float* __restrict__ out) {
    __shared__ float rowp[14 * MAXW];   // [ic][col] row-pooled maxes, 5376 B
    __shared__ float pooled[98];
    __shared__ float delta[4];

    const int b    = blockIdx.x;
    const int tid  = threadIdx.x;
    const int warp = tid >> 5;          // 0..6
    const int lane = tid & 31;

    const int y1 = __ldg(&coords[b * 4 + 0]);
    const int x1 = __ldg(&coords[b * 4 + 1]);
    const int h  = __ldg(&coords[b * 4 + 2]) - y1;
    const int w  = __ldg(&coords[b * 4 + 3]) - x1;

    // ---- Stage 1: warp computes TWO row-max slices (ic=warp, ic=warp+7) ----
    // float4 loads (1 LDG.128 per slice-row). Dynamic row bound: boxes only
    // pay for the bin rows they actually have (avg ~9, was fixed 14).
    {
        const int ax  = x1 & ~3;        // 16B-aligned column start
        const int off = x1 - ax;        // 0..3
        const int c0  = 4 * lane - off; // rowp column of element .x

        // lane active if it covers any column in [0, w)
        const bool act = (4 * lane) < (off + w);

        const int icA = warp,     icB = warp + 7;
        const int iA = icA >> 1,  cA = icA & 1;
        const int iB = icB >> 1,  cB = icB & 1;

        const int srA = (iA * h) / POOLW;
        const int nA  = ((iA + 1) * h + POOLW - 1) / POOLW - srA;
        const int srB = (iB * h) / POOLW;
        const int nB  = ((iB + 1) * h + POOLW - 1) / POOLW - srB;
        const int nmax = nA > nB ? nA : nB;

        const float4* pA = reinterpret_cast<const float4*>(
            feature + cA * IMG_HW + (y1 + srA) * IMG_W + ax) + lane;
        const float4* pB = reinterpret_cast<const float4*>(
            feature + cB * IMG_HW + (y1 + srB) * IMG_W + ax) + lane;

        float4 mA = make_float4(-FLT_MAX, -FLT_MAX, -FLT_MAX, -FLT_MAX);
        float4 mB = make_float4(-FLT_MAX, -FLT_MAX, -FLT_MAX, -FLT_MAX);

        #pragma unroll 4
        for (int k = 0; k < nmax; ++k) {
            if (act && k < nA) {
                const float4 v = pA[k * (IMG_W / 4)];
                mA.x = fmaxf(mA.x, v.x); mA.y = fmaxf(mA.y, v.y);
                mA.z = fmaxf(mA.z, v.z); mA.w = fmaxf(mA.w, v.w);
            }
            if (act && k < nB) {
                const float4 v = pB[k * (IMG_W / 4)];
                mB.x = fmaxf(mB.x, v.x); mB.y = fmaxf(mB.y, v.y);
                mB.z = fmaxf(mB.z, v.z); mB.w = fmaxf(mB.w, v.w);
            }
        }

        if (act) {
            float* dA = rowp + icA * MAXW;
            float* dB = rowp + icB * MAXW;
            if (c0     >= 0 && c0     < w) { dA[c0]     = mA.x; dB[c0]     = mB.x; }
            if (c0 + 1 >= 0 && c0 + 1 < w) { dA[c0 + 1] = mA.y; dB[c0 + 1] = mB.y; }
            if (c0 + 2 >= 0 && c0 + 2 < w) { dA[c0 + 2] = mA.z; dB[c0 + 2] = mB.z; }
            if (c0 + 3 >= 0 && c0 + 3 < w) { dA[c0 + 3] = mA.w; dB[c0 + 3] = mB.w; }
        }
    }
    __syncthreads();

    // ---- Stage 2: col-wise max over rowp -> pooled[c*49 + i*7 + j] ----
    if (tid < 98) {
        const int c   = tid / 49;
        const int rem = tid - c * 49;
        const int i   = rem / 7;
        const int j   = rem - i * 7;

        const int sc = (j * w) / POOLW;
        const int ec = ((j + 1) * w + POOLW - 1) / POOLW;

        const float* base = rowp + (i * 2 + c) * MAXW;
        float m = -FLT_MAX;
        for (int x = sc; x < ec; ++x)
            m = fmaxf(m, base[x]);
        pooled[tid] = m;
    }
    __syncthreads();

    // ---- FC(98 -> 4) + ReLU : warp o (0..3) computes output o ----
    if (warp < 4) {
        float acc = 0.0f;
        const float* wrow = fc_w + warp * 98;
        for (int k = lane; k < 98; k += 32)
            acc = fmaf(wrow[k], pooled[k], acc);
        #pragma unroll
        for (int off = 16; off > 0; off >>= 1)
            acc += __shfl_down_sync(0xFFFFFFFFu, acc, off);
        if (lane == 0)
            delta[warp] = fmaxf(acc + fc_b[warp], 0.0f);
    }
    __syncthreads();

    // ---- Output row: boxes copy, cols 2..5 += delta ----
    if (tid < 6) {
        float v = boxes[b * 6 + tid];
        if (tid >= 2) v += delta[tid - 2];
        out[b * 6 + tid] = v;
    }
}

extern "C" void kernel_launch(void* const* d_in, const int* in_sizes, int n_in,
                              void* d_out, int out_size) {
    const float* feature = (const float*)d_in[0];
    const float* boxes   = (const float*)d_in[1];
    const int*   coords  = (const int*)d_in[2];
    const float* fc_w    = (const float*)d_in[3];
    const float* fc_b    = (const float*)d_in[4];
    float* out = (float*)d_out;

    const int nbox = in_sizes[2] / 4;

    roi_pool_fc_kernel<<<nbox, NTHREADS>>>(feature, boxes, coords, fc_w, fc_b, out);
}

// round 15
// speedup vs baseline: 1.2391x; 1.2391x over previous
#include <cuda_runtime.h>
#include <float.h>

#define POOLW 7
#define IMG_W 2048
#define IMG_HW (2048 * 2048)
#define NTHREADS 224          // 7 warps; warp w owns slices ic = w and ic = w+7
#define MAXW 96
#define MAXROWS 14            // max adaptive-bin height for h <= 95

__global__ __launch_bounds__(NTHREADS)
void roi_pool_fc_kernel(const float* __restrict__ feature,
                        const float* __restrict__ boxes,
                        const int*   __restrict__ coords,
                        const float* __restrict__ fc_w,
                        const float* __restrict__ fc_b,
                        float* __restrict__ out) {
    __shared__ float rowp[14 * MAXW];   // [ic][col] row-pooled maxes, 5376 B
    __shared__ float pooled[98];

    const int b    = blockIdx.x;
    const int tid  = threadIdx.x;
    const int warp = tid >> 5;          // 0..6
    const int lane = tid & 31;

    const int y1 = __ldg(&coords[b * 4 + 0]);
    const int x1 = __ldg(&coords[b * 4 + 1]);
    const int h  = __ldg(&coords[b * 4 + 2]) - y1;
    const int w  = __ldg(&coords[b * 4 + 3]) - x1;

    // Delta-independent output cols 0,1: write immediately.
    if (tid < 2) out[b * 6 + tid] = boxes[b * 6 + tid];

    // ---- Stage 1: warp computes TWO row-max slices (ic=warp, ic=warp+7) ----
    // float4 loads, fixed 14-trip full unroll with predication: all 28 LDG.128
    // per warp are independent and front-batched (predicated-off loads issue
    // no memory traffic). Proven best for the timed regime.
    {
        const int ax  = x1 & ~3;        // 16B-aligned column start
        const int off = x1 - ax;        // 0..3
        const int c0  = 4 * lane - off; // rowp column of element .x

        const bool act = (4 * lane) < (off + w);

        const int icA = warp,     icB = warp + 7;
        const int iA = icA >> 1,  cA = icA & 1;
        const int iB = icB >> 1,  cB = icB & 1;

        const int srA = (iA * h) / POOLW;
        const int nA  = ((iA + 1) * h + POOLW - 1) / POOLW - srA;
        const int srB = (iB * h) / POOLW;
        const int nB  = ((iB + 1) * h + POOLW - 1) / POOLW - srB;

        const float4* pA = reinterpret_cast<const float4*>(
            feature + cA * IMG_HW + (y1 + srA) * IMG_W + ax) + lane;
        const float4* pB = reinterpret_cast<const float4*>(
            feature + cB * IMG_HW + (y1 + srB) * IMG_W + ax) + lane;

        float4 mA = make_float4(-FLT_MAX, -FLT_MAX, -FLT_MAX, -FLT_MAX);
        float4 mB = make_float4(-FLT_MAX, -FLT_MAX, -FLT_MAX, -FLT_MAX);

        #pragma unroll
        for (int k = 0; k < MAXROWS; ++k) {
            if (act && k < nA) {
                const float4 v = pA[k * (IMG_W / 4)];
                mA.x = fmaxf(mA.x, v.x); mA.y = fmaxf(mA.y, v.y);
                mA.z = fmaxf(mA.z, v.z); mA.w = fmaxf(mA.w, v.w);
            }
            if (act && k < nB) {
                const float4 v = pB[k * (IMG_W / 4)];
                mB.x = fmaxf(mB.x, v.x); mB.y = fmaxf(mB.y, v.y);
                mB.z = fmaxf(mB.z, v.z); mB.w = fmaxf(mB.w, v.w);
            }
        }

        if (act) {
            float* dA = rowp + icA * MAXW;
            float* dB = rowp + icB * MAXW;
            if (c0     >= 0 && c0     < w) { dA[c0]     = mA.x; dB[c0]     = mB.x; }
            if (c0 + 1 >= 0 && c0 + 1 < w) { dA[c0 + 1] = mA.y; dB[c0 + 1] = mB.y; }
            if (c0 + 2 >= 0 && c0 + 2 < w) { dA[c0 + 2] = mA.z; dB[c0 + 2] = mB.z; }
            if (c0 + 3 >= 0 && c0 + 3 < w) { dA[c0 + 3] = mA.w; dB[c0 + 3] = mB.w; }
        }
    }

    // ---- Stage 2 (warp-local, NO block barrier): the producing warp computes
    // the 7 col-bin maxes of each of its two slices. Lanes 0..6 -> slice A,
    // lanes 7..13 -> slice B. __syncwarp orders the rowp stores above.
    __syncwarp();
    if (lane < 14) {
        const int halfB = lane >= 7;
        const int ic = warp + 7 * halfB;
        const int j  = lane - 7 * halfB;
        const int i  = ic >> 1;
        const int c  = ic & 1;

        const int sc = (j * w) / POOLW;
        const int ec = ((j + 1) * w + POOLW - 1) / POOLW;

        const float* base = rowp + ic * MAXW;
        float m = -FLT_MAX;
        for (int x = sc; x < ec; ++x)
            m = fmaxf(m, base[x]);
        pooled[c * 49 + i * 7 + j] = m;
    }
    __syncthreads();   // the only full-CTA barrier

    // ---- FC(98 -> 4) + ReLU : warp o computes output o, writes gmem directly ----
    if (warp < 4) {
        float acc = 0.0f;
        const float* wrow = fc_w + warp * 98;
        for (int k = lane; k < 98; k += 32)
            acc = fmaf(wrow[k], pooled[k], acc);
        #pragma unroll
        for (int off = 16; off > 0; off >>= 1)
            acc += __shfl_down_sync(0xFFFFFFFFu, acc, off);
        if (lane == 0) {
            const float d = fmaxf(acc + fc_b[warp], 0.0f);
            out[b * 6 + 2 + warp] = boxes[b * 6 + 2 + warp] + d;
        }
    }
}

extern "C" void kernel_launch(void* const* d_in, const int* in_sizes, int n_in,
                              void* d_out, int out_size) {
    const float* feature = (const float*)d_in[0];
    const float* boxes   = (const float*)d_in[1];
    const int*   coords  = (const int*)d_in[2];
    const float* fc_w    = (const float*)d_in[3];
    const float* fc_b    = (const float*)d_in[4];
    float* out = (float*)d_out;

    const int nbox = in_sizes[2] / 4;

    roi_pool_fc_kernel<<<nbox, NTHREADS>>>(feature, boxes, coords, fc_w, fc_b, out);
}